// round 2
// baseline (speedup 1.0000x reference)
#include <cuda_runtime.h>
#include <cuda_bf16.h>
#include <cstdint>
#include <cstddef>

#define BB   32
#define SS   512
#define EE   512
#define HH   1024
#define G3   3072
#define NBLK 128      // persistent CTAs, all resident in wave 1 (<=148 SMs)

// ---------------- device scratch (no allocations allowed) -------------------
__device__ float g_xw[(size_t)BB * SS * G3];   // [B][S][3H] input projections
__device__ float g_h[2][HH * BB];              // double-buffered h, k-major [H][B]
__device__ unsigned int g_bar_count;
__device__ unsigned int g_bar_gen;

// ---------------- packed fp32x2 helpers (Blackwell) -------------------------
__device__ __forceinline__ unsigned long long ffma2(unsigned long long a,
                                                    unsigned long long b,
                                                    unsigned long long c) {
    unsigned long long d;
    asm("fma.rn.f32x2 %0, %1, %2, %3;" : "=l"(d) : "l"(a), "l"(b), "l"(c));
    return d;
}
__device__ __forceinline__ unsigned long long pack2dup(float x) {
    unsigned long long r;
    asm("mov.b64 %0, {%1, %1};" : "=l"(r) : "f"(x));
    return r;
}
__device__ __forceinline__ float2 unpack2(unsigned long long v) {
    float lo, hi;
    asm("mov.b64 {%0, %1}, %2;" : "=f"(lo), "=f"(hi) : "l"(v));
    return make_float2(lo, hi);
}

// =====================  Phase A: xw = emb[x] @ W + b_i  =====================
// 128x128 tile, BK=8, 256 threads, 8x8 microtile, f32x2 accumulate.
__global__ void __launch_bounds__(256) xw_gemm_kernel(
    const int* __restrict__ x, const float* __restrict__ emb,
    const float* __restrict__ W, const float* __restrict__ b_i)
{
    __shared__ __align__(16) float As[8][128];   // [k][m]
    __shared__ __align__(16) float Bs[8][128];   // [k][n]
    __shared__ int xi[128];

    const int tid = threadIdx.x;
    const int m0 = blockIdx.y * 128;
    const int n0 = blockIdx.x * 128;
    if (tid < 128) xi[tid] = x[m0 + tid];

    const int tm = (tid >> 4) << 3;
    const int tn = (tid & 15) << 3;

    unsigned long long acc[8][4];
    #pragma unroll
    for (int i = 0; i < 8; i++)
        #pragma unroll
        for (int q = 0; q < 4; q++) acc[i][q] = 0ull;

    const int am = tid >> 1, ak = (tid & 1) << 2;
    const int bk = tid >> 5, bn = (tid & 31) << 2;
    __syncthreads();

    for (int k0 = 0; k0 < EE; k0 += 8) {
        float4 av = *(const float4*)(emb + (size_t)xi[am] * EE + k0 + ak);
        float4 bv = *(const float4*)(W + (size_t)(k0 + bk) * G3 + n0 + bn);
        As[ak + 0][am] = av.x; As[ak + 1][am] = av.y;
        As[ak + 2][am] = av.z; As[ak + 3][am] = av.w;
        *(float4*)&Bs[bk][bn] = bv;
        __syncthreads();

        #pragma unroll
        for (int k = 0; k < 8; k++) {
            float4 a0 = *(const float4*)&As[k][tm];
            float4 a1 = *(const float4*)&As[k][tm + 4];
            unsigned long long bp0 = *(const unsigned long long*)&Bs[k][tn + 0];
            unsigned long long bp1 = *(const unsigned long long*)&Bs[k][tn + 2];
            unsigned long long bp2 = *(const unsigned long long*)&Bs[k][tn + 4];
            unsigned long long bp3 = *(const unsigned long long*)&Bs[k][tn + 6];
            float aa[8] = {a0.x, a0.y, a0.z, a0.w, a1.x, a1.y, a1.z, a1.w};
            #pragma unroll
            for (int i = 0; i < 8; i++) {
                unsigned long long ad = pack2dup(aa[i]);
                acc[i][0] = ffma2(ad, bp0, acc[i][0]);
                acc[i][1] = ffma2(ad, bp1, acc[i][1]);
                acc[i][2] = ffma2(ad, bp2, acc[i][2]);
                acc[i][3] = ffma2(ad, bp3, acc[i][3]);
            }
        }
        __syncthreads();
    }

    float4 bi0 = *(const float4*)(b_i + n0 + tn);
    float4 bi1 = *(const float4*)(b_i + n0 + tn + 4);
    #pragma unroll
    for (int i = 0; i < 8; i++) {
        float2 c0 = unpack2(acc[i][0]), c1 = unpack2(acc[i][1]);
        float2 c2 = unpack2(acc[i][2]), c3 = unpack2(acc[i][3]);
        float4 o0 = make_float4(c0.x + bi0.x, c0.y + bi0.y, c1.x + bi0.z, c1.y + bi0.w);
        float4 o1 = make_float4(c2.x + bi1.x, c2.y + bi1.y, c3.x + bi1.z, c3.y + bi1.w);
        size_t row = (size_t)(m0 + tm + i);
        *(float4*)(g_xw + row * G3 + n0 + tn)     = o0;
        *(float4*)(g_xw + row * G3 + n0 + tn + 4) = o1;
    }
}

// =====================  Phase B: persistent GRU scan  =======================
__device__ __forceinline__ void grid_barrier() {
    __threadfence();
    __syncthreads();
    if (threadIdx.x == 0) {
        unsigned my = *((volatile unsigned*)&g_bar_gen);
        unsigned prev = atomicAdd(&g_bar_count, 1u);
        if (prev == NBLK - 1u) {
            g_bar_count = 0u;
            __threadfence();
            atomicAdd(&g_bar_gen, 1u);
        } else {
            while (*((volatile unsigned*)&g_bar_gen) == my) {}
        }
    }
    __syncthreads();
}

// smem: U_s[24][1024] + h_s[1024][32] + xws[24][32]  = 232448 B (== 227 KB cap)
#define SMEM_B ((24 * 1024 + 1024 * 32 + 24 * 32) * 4)

__global__ void __launch_bounds__(256) gru_persistent(
    const float* __restrict__ U, const float* __restrict__ b_h,
    float* __restrict__ out)
{
    extern __shared__ float sm[];
    float* U_s = sm;                   // [c][k], c = g*8 + wi
    float* h_s = sm + 24 * 1024;       // [k][b]
    float* xws = h_s + 1024 * 32;      // [c][b]; reused as hn[w][b] after compute

    const int tid = threadIdx.x;
    const int blk = blockIdx.x;
    const int w = tid >> 5, l = tid & 31;
    const int j = blk * 8 + w;

    // One-time: load this CTA's 24 U columns into smem (transposed to [c][k]).
    for (int c = 0; c < 24; c++) {
        int colg = (c >> 3) * HH + blk * 8 + (c & 7);
        for (int k = tid; k < HH; k += 256)
            U_s[c * 1024 + k] = U[(size_t)k * G3 + colg];
    }
    const float bhz = b_h[j], bhr = b_h[HH + j], bhh = b_h[2 * HH + j];
    const float* Uz = U_s + (0 * 8 + w) * 1024;
    const float* Ur = U_s + (1 * 8 + w) * 1024;
    const float* Uh = U_s + (2 * 8 + w) * 1024;

    int p = 0;
    grid_barrier();   // also ensures U_s ready before compute (local sync inside)

    for (int s = 0; s < SS; s++) {
        // --- stage h(t-1) into smem [k][b] (k-major global, coalesced) ---
        if (s == 0) {
            float4 z4 = make_float4(0.f, 0.f, 0.f, 0.f);
            for (int i = tid; i < HH * BB / 4; i += 256) ((float4*)h_s)[i] = z4;
        } else {
            const float4* src = (const float4*)(g_h[p]);
            for (int i = tid; i < HH * BB / 4; i += 256)
                ((float4*)h_s)[i] = __ldcg(src + i);
        }
        // --- stage xw_t for this CTA's 24 columns: [c][b] ---
        if (tid < 96) {
            int b = tid / 3, g = tid % 3;
            const float* srcp = g_xw + ((size_t)b * SS + s) * G3 + g * HH + blk * 8;
            float4 v0 = *(const float4*)(srcp);
            float4 v1 = *(const float4*)(srcp + 4);
            float vv[8] = {v0.x, v0.y, v0.z, v0.w, v1.x, v1.y, v1.z, v1.w};
            #pragma unroll
            for (int ii = 0; ii < 8; ii++)
                xws[(g * 8 + ii) * 32 + b] = vv[ii];
        }
        __syncthreads();

        // --- hu[l][j] = sum_k h[l][k] * U[k][col]  (lane = batch) ---
        float az = 0.f, ar = 0.f, ah = 0.f;
        #pragma unroll 8
        for (int k = 0; k < HH; k += 4) {
            float4 uz = *(const float4*)(Uz + k);
            float4 ur = *(const float4*)(Ur + k);
            float4 uh = *(const float4*)(Uh + k);
            float h0 = h_s[(k + 0) * 32 + l];
            float h1 = h_s[(k + 1) * 32 + l];
            float h2 = h_s[(k + 2) * 32 + l];
            float h3 = h_s[(k + 3) * 32 + l];
            az += h0 * uz.x + h1 * uz.y + h2 * uz.z + h3 * uz.w;
            ar += h0 * ur.x + h1 * ur.y + h2 * ur.z + h3 * ur.w;
            ah += h0 * uh.x + h1 * uh.y + h2 * uh.z + h3 * uh.w;
        }

        const float xz = xws[(0 * 8 + w) * 32 + l];
        const float xr = xws[(1 * 8 + w) * 32 + l];
        const float xh = xws[(2 * 8 + w) * 32 + l];
        const float huz = az + bhz, hur = ar + bhr, huh = ah + bhh;
        const float zg = 1.f / (1.f + expf(-(xz + huz)));
        const float rg = 1.f / (1.f + expf(-(xr + hur)));
        const float hh = tanhf(xh + rg * huh);
        const float hp = h_s[j * 32 + l];           // wait: h_s is [k][b] = [j][l]? no!
        const float hn = zg * hp + (1.f - zg) * hh;

        __stcg(&g_h[p ^ 1][j * 32 + l], hn);

        __syncthreads();            // all xws reads done -> safe to reuse
        xws[w * 32 + l] = hn;       // hn[w][b]
        __syncthreads();
        if (tid < 32) {             // coalesced 32B output chunks per batch
            int b = tid;
            float4 v0 = make_float4(xws[0 * 32 + b], xws[1 * 32 + b],
                                    xws[2 * 32 + b], xws[3 * 32 + b]);
            float4 v1 = make_float4(xws[4 * 32 + b], xws[5 * 32 + b],
                                    xws[6 * 32 + b], xws[7 * 32 + b]);
            float4* dst = (float4*)(out + ((size_t)b * SS + s) * HH + blk * 8);
            dst[0] = v0; dst[1] = v1;
        }
        p ^= 1;
        grid_barrier();
    }
}

extern "C" void kernel_launch(void* const* d_in, const int* in_sizes, int n_in,
                              void* d_out, int out_size) {
    const int*   x   = (const int*)d_in[0];
    const float* emb = (const float*)d_in[1];
    const float* W   = (const float*)d_in[2];
    const float* U   = (const float*)d_in[3];
    const float* b_i = (const float*)d_in[4];
    const float* b_h = (const float*)d_in[5];
    float* out = (float*)d_out;

    dim3 gA(G3 / 128, (BB * SS) / 128);   // (24, 128)
    xw_gemm_kernel<<<gA, 256>>>(x, emb, W, b_i);

    cudaFuncSetAttribute(gru_persistent,
                         cudaFuncAttributeMaxDynamicSharedMemorySize, SMEM_B);
    gru_persistent<<<NBLK, 256, SMEM_B>>>(U, b_h, out);
}

// round 5
// speedup vs baseline: 1.4465x; 1.4465x over previous
#include <cuda_runtime.h>
#include <cuda_bf16.h>
#include <cstdint>
#include <cstddef>

#define BB   32
#define SS   512
#define EE   512
#define HH   1024
#define G3   3072
#define NBLK 128      // persistent CTAs, all resident in wave 1 (<=148 SMs)

// ---------------- device scratch (no allocations allowed) -------------------
__device__ float g_xw[(size_t)BB * SS * G3];   // [B][S][3H] input projections
// h in pair-interleaved layout: pos = (j>>1)*64 + b*2 + (j&1)
__device__ float g_h[2][HH * BB];
__device__ unsigned int g_bar_count;
__device__ unsigned int g_bar_gen;

// ---------------- packed fp32x2 helpers (Blackwell) -------------------------
__device__ __forceinline__ unsigned long long ffma2(unsigned long long a,
                                                    unsigned long long b,
                                                    unsigned long long c) {
    unsigned long long d;
    asm("fma.rn.f32x2 %0, %1, %2, %3;" : "=l"(d) : "l"(a), "l"(b), "l"(c));
    return d;
}
__device__ __forceinline__ unsigned long long pack2dup(float x) {
    unsigned long long r;
    asm("mov.b64 %0, {%1, %1};" : "=l"(r) : "f"(x));
    return r;
}
__device__ __forceinline__ float2 unpack2(unsigned long long v) {
    float lo, hi;
    asm("mov.b64 {%0, %1}, %2;" : "=f"(lo), "=f"(hi) : "l"(v));
    return make_float2(lo, hi);
}

// =====================  Phase A: xw = emb[x] @ W + b_i  =====================
// 128x128 tile, BK=8, 256 threads, 8x8 microtile, f32x2 accumulate.
__global__ void __launch_bounds__(256) xw_gemm_kernel(
    const int* __restrict__ x, const float* __restrict__ emb,
    const float* __restrict__ W, const float* __restrict__ b_i)
{
    __shared__ __align__(16) float As[8][128];   // [k][m]
    __shared__ __align__(16) float Bs[8][128];   // [k][n]
    __shared__ int xi[128];

    const int tid = threadIdx.x;
    const int m0 = blockIdx.y * 128;
    const int n0 = blockIdx.x * 128;
    if (tid < 128) xi[tid] = x[m0 + tid];

    const int tm = (tid >> 4) << 3;
    const int tn = (tid & 15) << 3;

    unsigned long long acc[8][4];
    #pragma unroll
    for (int i = 0; i < 8; i++)
        #pragma unroll
        for (int q = 0; q < 4; q++) acc[i][q] = 0ull;

    const int am = tid >> 1, ak = (tid & 1) << 2;
    const int bk = tid >> 5, bn = (tid & 31) << 2;
    __syncthreads();

    for (int k0 = 0; k0 < EE; k0 += 8) {
        float4 av = *(const float4*)(emb + (size_t)xi[am] * EE + k0 + ak);
        float4 bv = *(const float4*)(W + (size_t)(k0 + bk) * G3 + n0 + bn);
        As[ak + 0][am] = av.x; As[ak + 1][am] = av.y;
        As[ak + 2][am] = av.z; As[ak + 3][am] = av.w;
        *(float4*)&Bs[bk][bn] = bv;
        __syncthreads();

        #pragma unroll
        for (int k = 0; k < 8; k++) {
            float4 a0 = *(const float4*)&As[k][tm];
            float4 a1 = *(const float4*)&As[k][tm + 4];
            unsigned long long bp0 = *(const unsigned long long*)&Bs[k][tn + 0];
            unsigned long long bp1 = *(const unsigned long long*)&Bs[k][tn + 2];
            unsigned long long bp2 = *(const unsigned long long*)&Bs[k][tn + 4];
            unsigned long long bp3 = *(const unsigned long long*)&Bs[k][tn + 6];
            float aa[8] = {a0.x, a0.y, a0.z, a0.w, a1.x, a1.y, a1.z, a1.w};
            #pragma unroll
            for (int i = 0; i < 8; i++) {
                unsigned long long ad = pack2dup(aa[i]);
                acc[i][0] = ffma2(ad, bp0, acc[i][0]);
                acc[i][1] = ffma2(ad, bp1, acc[i][1]);
                acc[i][2] = ffma2(ad, bp2, acc[i][2]);
                acc[i][3] = ffma2(ad, bp3, acc[i][3]);
            }
        }
        __syncthreads();
    }

    float4 bi0 = *(const float4*)(b_i + n0 + tn);
    float4 bi1 = *(const float4*)(b_i + n0 + tn + 4);
    #pragma unroll
    for (int i = 0; i < 8; i++) {
        float2 c0 = unpack2(acc[i][0]), c1 = unpack2(acc[i][1]);
        float2 c2 = unpack2(acc[i][2]), c3 = unpack2(acc[i][3]);
        float4 o0 = make_float4(c0.x + bi0.x, c0.y + bi0.y, c1.x + bi0.z, c1.y + bi0.w);
        float4 o1 = make_float4(c2.x + bi1.x, c2.y + bi1.y, c3.x + bi1.z, c3.y + bi1.w);
        size_t row = (size_t)(m0 + tm + i);
        *(float4*)(g_xw + row * G3 + n0 + tn)     = o0;
        *(float4*)(g_xw + row * G3 + n0 + tn + 4) = o1;
    }
}

// =====================  Phase B: persistent GRU scan  =======================
__device__ __forceinline__ void grid_barrier() {
    __threadfence();
    __syncthreads();
    if (threadIdx.x == 0) {
        unsigned my = *((volatile unsigned*)&g_bar_gen);
        unsigned prev = atomicAdd(&g_bar_count, 1u);
        if (prev == NBLK - 1u) {
            g_bar_count = 0u;
            __threadfence();
            atomicAdd(&g_bar_gen, 1u);
        } else {
            while (*((volatile unsigned*)&g_bar_gen) == my) { __nanosleep(64); }
        }
    }
    __syncthreads();
}

// smem: U_s[24][1024] (96KB) + h2_s[512][32][2] (128KB) + xws[24][32] (3KB)
// red[8][24][32] (24KB) aliases the front of h2_s (h2_s fully consumed first).
#define SMEM_B ((24 * 1024 + 1024 * 32 + 24 * 32) * 4)

__global__ void __launch_bounds__(256) gru_persistent(
    const float* __restrict__ U, const float* __restrict__ b_h,
    float* __restrict__ out)
{
    extern __shared__ float sm[];
    float* U_s  = sm;                       // [c][k], c = g*8 + jl
    float* h2_s = sm + 24 * 1024;           // [kpair][b][2]
    float* red  = h2_s;                     // alias: [w][c][b]
    float* xws  = sm + 24 * 1024 + HH * BB; // [c][b]; later hn[jl][b]

    const int tid = threadIdx.x;
    const int blk = blockIdx.x;
    const int w = tid >> 5, l = tid & 31;   // w: warp (k-slice / jl), l: batch
    const int j = blk * 8 + w;              // this thread's output unit (epilogue)

    // One-time: load this CTA's 24 U columns into smem [c][k].
    for (int c = 0; c < 24; c++) {
        int colg = (c >> 3) * HH + blk * 8 + (c & 7);
        for (int k = tid; k < HH; k += 256)
            U_s[c * 1024 + k] = U[(size_t)k * G3 + colg];
    }
    const float bhz = b_h[j], bhr = b_h[HH + j], bhh = b_h[2 * HH + j];
    const int hpos = (j >> 1) * 64 + l * 2 + (j & 1);   // pair-layout index of (j,l)

    int p = 0;
    grid_barrier();   // U_s ready (internal __syncthreads) + phase A ordering

    for (int s = 0; s < SS; s++) {
        // ---- stage h(t-1) into smem (verbatim copy, pair layout) ----
        if (s == 0) {
            float4 z4 = make_float4(0.f, 0.f, 0.f, 0.f);
            for (int i = tid; i < HH * BB / 4; i += 256) ((float4*)h2_s)[i] = z4;
        } else {
            const float4* src = (const float4*)(g_h[p]);
            for (int i = tid; i < HH * BB / 4; i += 256)
                ((float4*)h2_s)[i] = __ldcg(src + i);
        }
        // ---- stage xw_t for this CTA's 24 columns: [c][b] ----
        if (tid < 96) {
            int b = tid / 3, g = tid % 3;
            const float* srcp = g_xw + ((size_t)b * SS + s) * G3 + g * HH + blk * 8;
            float4 v0 = *(const float4*)(srcp);
            float4 v1 = *(const float4*)(srcp + 4);
            float vv[8] = {v0.x, v0.y, v0.z, v0.w, v1.x, v1.y, v1.z, v1.w};
            #pragma unroll
            for (int ii = 0; ii < 8; ii++)
                xws[(g * 8 + ii) * 32 + b] = vv[ii];
        }
        __syncthreads();

        // ---- warp w: partial dots over k-slice [w*128, w*128+128), all 24 cols
        unsigned long long acc[24];
        #pragma unroll
        for (int c = 0; c < 24; c++) acc[c] = 0ull;

        #pragma unroll 4
        for (int q = 0; q < 64; q += 2) {           // two k-pairs = 4 k per iter
            int kp = w * 64 + q;
            unsigned long long hp0 =
                *(const unsigned long long*)(h2_s + (size_t)kp * 64 + l * 2);
            unsigned long long hp1 =
                *(const unsigned long long*)(h2_s + (size_t)(kp + 1) * 64 + l * 2);
            int k = w * 128 + q * 2;
            #pragma unroll
            for (int c = 0; c < 24; c++) {
                ulonglong2 uv = *(const ulonglong2*)(U_s + c * 1024 + k);
                acc[c] = ffma2(hp0, uv.x, acc[c]);
                acc[c] = ffma2(hp1, uv.y, acc[c]);
            }
        }

        const float hp_prev = h2_s[hpos];   // grab before red aliases h2_s
        __syncthreads();                    // all warps done reading h2_s

        #pragma unroll
        for (int c = 0; c < 24; c++) {
            float2 v = unpack2(acc[c]);
            red[w * 768 + c * 32 + l] = v.x + v.y;
        }
        __syncthreads();

        // ---- epilogue: thread (jl=w, b=l) sums 8 warp partials per gate ----
        float az = 0.f, ar = 0.f, ah = 0.f;
        #pragma unroll
        for (int ww = 0; ww < 8; ww++) {
            az += red[ww * 768 + (0 * 8 + w) * 32 + l];
            ar += red[ww * 768 + (1 * 8 + w) * 32 + l];
            ah += red[ww * 768 + (2 * 8 + w) * 32 + l];
        }
        const float xz = xws[(0 * 8 + w) * 32 + l];
        const float xr = xws[(1 * 8 + w) * 32 + l];
        const float xh = xws[(2 * 8 + w) * 32 + l];
        const float zg = 1.f / (1.f + expf(-(xz + az + bhz)));
        const float rg = 1.f / (1.f + expf(-(xr + ar + bhr)));
        const float hh = tanhf(xh + rg * (ah + bhh));
        const float hn = zg * hp_prev + (1.f - zg) * hh;

        __stcg(&g_h[p ^ 1][hpos], hn);

        __syncthreads();            // xws gate-reads done -> safe to overwrite
        xws[w * 32 + l] = hn;       // hn[jl][b]
        __syncthreads();
        if (tid < 32) {             // coalesced 32B output chunks per batch
            int b = tid;
            float4 v0 = make_float4(xws[0 * 32 + b], xws[1 * 32 + b],
                                    xws[2 * 32 + b], xws[3 * 32 + b]);
            float4 v1 = make_float4(xws[4 * 32 + b], xws[5 * 32 + b],
                                    xws[6 * 32 + b], xws[7 * 32 + b]);
            float4* dst = (float4*)(out + ((size_t)b * SS + s) * HH + blk * 8);
            dst[0] = v0; dst[1] = v1;
        }
        p ^= 1;
        grid_barrier();
    }
}

extern "C" void kernel_launch(void* const* d_in, const int* in_sizes, int n_in,
                              void* d_out, int out_size) {
    const int*   x   = (const int*)d_in[0];
    const float* emb = (const float*)d_in[1];
    const float* W   = (const float*)d_in[2];
    const float* U   = (const float*)d_in[3];
    const float* b_i = (const float*)d_in[4];
    const float* b_h = (const float*)d_in[5];
    float* out = (float*)d_out;

    dim3 gA(G3 / 128, (BB * SS) / 128);   // (24, 128)
    xw_gemm_kernel<<<gA, 256>>>(x, emb, W, b_i);

    cudaFuncSetAttribute(gru_persistent,
                         cudaFuncAttributeMaxDynamicSharedMemorySize, SMEM_B);
    gru_persistent<<<NBLK, 256, SMEM_B>>>(U, b_h, out);
}